// round 3
// baseline (speedup 1.0000x reference)
#include <cuda_runtime.h>
#include <math.h>

#define BSZ 16
#define CW  32
#define MY  180
#define NX  360
#define KM  32
#define PLANE (MY*NX)
#define PIX (BSZ*PLANE)

typedef unsigned long long ull;

// ---------------- f32x2 helpers ----------------
__device__ __forceinline__ ull pk2(float lo, float hi) {
    ull r; asm("mov.b64 %0,{%1,%2};" : "=l"(r) : "f"(lo), "f"(hi)); return r;
}
__device__ __forceinline__ void fma2(ull& d, ull a, ull b) {
    asm("fma.rn.f32x2 %0,%1,%2,%0;" : "+l"(d) : "l"(a), "l"(b));
}
__device__ __forceinline__ float2 up2(ull v) {
    float2 r; asm("mov.b64 {%0,%1},%2;" : "=f"(r.x), "=f"(r.y) : "l"(v)); return r;
}
__device__ __forceinline__ float geluf(float x) {
    return 0.5f * x * (1.0f + erff(x * 0.70710678118654752f));
}

// ---------------- device scratch ----------------
__device__ __align__(16) float g_h  [BSZ*CW*PLANE];
__device__ __align__(16) float g_x1 [BSZ*CW*PLANE];
__device__ __align__(16) float g_ftyr[BSZ*CW*KM*NX];
__device__ __align__(16) float g_ftyi[BSZ*CW*KM*NX];
__device__ __align__(16) float g_oyr [BSZ*CW*KM*NX];
__device__ __align__(16) float g_oyi [BSZ*CW*KM*NX];
__device__ __align__(16) float g_ftxr[BSZ*CW*KM*MY];
__device__ __align__(16) float g_ftxi[BSZ*CW*KM*MY];
__device__ __align__(16) float g_oxr [BSZ*CW*KM*MY];
__device__ __align__(16) float g_oxi [BSZ*CW*KM*MY];
__device__ __align__(16) float g_Vyr [KM*MY], g_Vyi [KM*MY];   // [k][m]
__device__ __align__(16) float g_Vymr[MY*KM], g_Vymi[MY*KM];   // [m][k]
__device__ __align__(16) float g_Vxr [KM*NX], g_Vxi [KM*NX];   // [k][n]
__device__ __align__(16) float g_Vxnr[NX*KM], g_Vxni[NX*KM];   // [n][k]
__device__ float g_gx[NX], g_gy[MY];

// ---------------- precompute ----------------
__global__ void precomputeK(const float* __restrict__ sx,
                            const float* __restrict__ sy) {
    int t = blockIdx.x * blockDim.x + threadIdx.x;
    int stride = gridDim.x * blockDim.x;
    float x0 = sx[0], xL = sx[NX - 1];
    float y0 = sy[0], yL = sy[MY - 1];
    float invRX = 1.0f / (xL - x0), invRY = 1.0f / (yL - y0);
    float invSqN = rsqrtf((float)NX), invSqM = rsqrtf((float)MY);
    const float TWO_PI = 6.283185307179586f;

    for (int idx = t; idx < KM * NX; idx += stride) {
        int k = idx / NX, n = idx % NX;
        float p = (sx[n] - x0) * invRX;
        float s, c; sincosf(-TWO_PI * (float)k * p, &s, &c);
        float vr = c * invSqN, vi = s * invSqN;
        g_Vxr[idx] = vr; g_Vxi[idx] = vi;
        g_Vxnr[n * KM + k] = vr; g_Vxni[n * KM + k] = vi;
    }
    for (int idx = t; idx < KM * MY; idx += stride) {
        int k = idx / MY, m = idx % MY;
        float p = (sy[m] - y0) * invRY;
        float s, c; sincosf(-TWO_PI * (float)k * p, &s, &c);
        float vr = c * invSqM, vi = s * invSqM;
        g_Vyr[idx] = vr; g_Vyi[idx] = vi;
        g_Vymr[m * KM + k] = vr; g_Vymi[m * KM + k] = vi;
    }
    for (int n = t; n < NX; n += stride) g_gx[n] = (sx[n] - x0) / xL;
    for (int m = t; m < MY; m += stride) g_gy[m] = (sy[m] - y0) / yL;
}

// ---------------- fc0: tile 128 pixels, GEMM K=18 ----------------
__global__ void fc0K(const float* __restrict__ x,
                     const float* __restrict__ w,
                     const float* __restrict__ bias) {
    __shared__ float sX[18][128];
    __shared__ float sW[18][32];
    __shared__ float sB[32];
    int tid = threadIdx.x;
    for (int idx = tid; idx < 18 * 32; idx += 256) sW[idx >> 5][idx & 31] = w[idx];
    if (tid < 32) sB[tid] = bias[tid];

    int p0 = blockIdx.x * 128;
    {
        int pp = tid & 127, hf = tid >> 7;
        int p = p0 + pp;
        const float4* xp = (const float4*)(x + (size_t)p * 16) + hf * 2;
        float4 a = xp[0], b4 = xp[1];
        int c0 = hf * 8;
        sX[c0 + 0][pp] = a.x;  sX[c0 + 1][pp] = a.y;
        sX[c0 + 2][pp] = a.z;  sX[c0 + 3][pp] = a.w;
        sX[c0 + 4][pp] = b4.x; sX[c0 + 5][pp] = b4.y;
        sX[c0 + 6][pp] = b4.z; sX[c0 + 7][pp] = b4.w;
        if (hf == 0) {
            int mn = p % PLANE;
            sX[16][pp] = g_gx[mn % NX];
            sX[17][pp] = g_gy[mn / NX];
        }
    }
    __syncthreads();

    int og = tid >> 5, pg = tid & 31;
    ull t[4][2];
#pragma unroll
    for (int a = 0; a < 4; a++) { float bb = sB[og * 4 + a]; t[a][0] = t[a][1] = pk2(bb, bb); }

#pragma unroll 2
    for (int c = 0; c < 18; c++) {
        float4 x4 = *(const float4*)&sX[c][pg * 4];
        ull x01 = pk2(x4.x, x4.y), x23 = pk2(x4.z, x4.w);
        float4 w4 = *(const float4*)&sW[c][og * 4];
        const float* wv = &w4.x;
#pragma unroll
        for (int a = 0; a < 4; a++) {
            ull wd = pk2(wv[a], wv[a]);
            fma2(t[a][0], wd, x01);
            fma2(t[a][1], wd, x23);
        }
    }
#pragma unroll
    for (int a = 0; a < 4; a++) {
        int o = og * 4 + a;
        float2 u0 = up2(t[a][0]), u1 = up2(t[a][1]);
        float v[4] = {u0.x, u0.y, u1.x, u1.y};
#pragma unroll
        for (int j = 0; j < 4; j++) {
            int p = p0 + pg * 4 + j;
            int b = p / PLANE, mn = p % PLANE;
            g_h[((size_t)b * CW + o) * PLANE + mn] = v[j];
        }
    }
}

// ---------------- fty: per (b,i): FTY[k32][n] = Vy[k][m] x H[m][n] ----------------
__global__ void ftyK() {
    int bi = blockIdx.y;
    int n0 = blockIdx.x * 128;
    int tid = threadIdx.x;
    int kg = tid >> 5, ng = tid & 31;

    __shared__ float4 sH[20][32];
    __shared__ float4 sVr[20][8], sVi[20][8];

    ull cr[4][2], ci[4][2];
#pragma unroll
    for (int a = 0; a < 4; a++) { cr[a][0] = cr[a][1] = 0ULL; ci[a][0] = ci[a][1] = 0ULL; }

    const float* hb = g_h + (size_t)bi * PLANE;

    for (int m0 = 0; m0 < MY; m0 += 20) {
        for (int idx = tid; idx < 640; idx += 256) {
            int mm = idx >> 5, n4 = idx & 31;
            int gn = n0 + n4 * 4;
            sH[mm][n4] = (gn < NX) ? *(const float4*)&hb[(m0 + mm) * NX + gn]
                                   : make_float4(0.f, 0.f, 0.f, 0.f);
        }
        for (int idx = tid; idx < 160; idx += 256) {
            int mm = idx >> 3, k4 = idx & 7;
            sVr[mm][k4] = *(const float4*)&g_Vymr[(m0 + mm) * KM + k4 * 4];
            sVi[mm][k4] = *(const float4*)&g_Vymi[(m0 + mm) * KM + k4 * 4];
        }
        __syncthreads();
#pragma unroll 4
        for (int mm = 0; mm < 20; mm++) {
            float4 h4 = sH[mm][ng];
            ull h01 = pk2(h4.x, h4.y), h23 = pk2(h4.z, h4.w);
            float4 vr = sVr[mm][kg], vi = sVi[mm][kg];
            const float* vrp = &vr.x; const float* vip = &vi.x;
#pragma unroll
            for (int a = 0; a < 4; a++) {
                ull vrd = pk2(vrp[a], vrp[a]);
                ull vid = pk2(vip[a], vip[a]);
                fma2(cr[a][0], vrd, h01); fma2(cr[a][1], vrd, h23);
                fma2(ci[a][0], vid, h01); fma2(ci[a][1], vid, h23);
            }
        }
        __syncthreads();
    }
    int n = n0 + ng * 4;
    if (n < NX) {
#pragma unroll
        for (int a = 0; a < 4; a++) {
            int k = kg * 4 + a;
            size_t off = ((size_t)bi * KM + k) * NX + n;
            float2 r0 = up2(cr[a][0]), r1 = up2(cr[a][1]);
            float2 i0 = up2(ci[a][0]), i1 = up2(ci[a][1]);
            *(float4*)&g_ftyr[off] = make_float4(r0.x, r0.y, r1.x, r1.y);
            *(float4*)&g_ftyi[off] = make_float4(i0.x, i0.y, i1.x, i1.y);
        }
    }
}

// ---------------- ftx: per (b,i): FTX[k32][m] = sum_n Vx[k][n] H[m][n] ----------------
__global__ void ftxK() {
    int bi = blockIdx.y;
    int m0 = blockIdx.x * 128;
    int tid = threadIdx.x;
    int kg = tid >> 5, mg = tid & 31;

    __shared__ float4 sVr[36][8], sVi[36][8];
    __shared__ float  sHT[36][132];

    ull cr[4][2], ci[4][2];
#pragma unroll
    for (int a = 0; a < 4; a++) { cr[a][0] = cr[a][1] = 0ULL; ci[a][0] = ci[a][1] = 0ULL; }

    const float* hb = g_h + (size_t)bi * PLANE;

    for (int n0 = 0; n0 < NX; n0 += 36) {
        for (int idx = tid; idx < 1152; idx += 256) {
            int m = idx / 9, q = idx % 9;
            int gm = m0 + m;
            float4 v = (gm < MY) ? *(const float4*)&hb[gm * NX + n0 + q * 4]
                                 : make_float4(0.f, 0.f, 0.f, 0.f);
            int nn = q * 4;
            sHT[nn][m] = v.x; sHT[nn + 1][m] = v.y;
            sHT[nn + 2][m] = v.z; sHT[nn + 3][m] = v.w;
        }
        for (int idx = tid; idx < 288; idx += 256) {
            int nn = idx >> 3, k4 = idx & 7;
            sVr[nn][k4] = *(const float4*)&g_Vxnr[(n0 + nn) * KM + k4 * 4];
            sVi[nn][k4] = *(const float4*)&g_Vxni[(n0 + nn) * KM + k4 * 4];
        }
        __syncthreads();
#pragma unroll 4
        for (int nn = 0; nn < 36; nn++) {
            float4 h4 = *(const float4*)&sHT[nn][mg * 4];
            ull h01 = pk2(h4.x, h4.y), h23 = pk2(h4.z, h4.w);
            float4 vr = sVr[nn][kg], vi = sVi[nn][kg];
            const float* vrp = &vr.x; const float* vip = &vi.x;
#pragma unroll
            for (int a = 0; a < 4; a++) {
                ull vrd = pk2(vrp[a], vrp[a]);
                ull vid = pk2(vip[a], vip[a]);
                fma2(cr[a][0], vrd, h01); fma2(cr[a][1], vrd, h23);
                fma2(ci[a][0], vid, h01); fma2(ci[a][1], vid, h23);
            }
        }
        __syncthreads();
    }
    int m = m0 + mg * 4;
    if (m < MY) {
#pragma unroll
        for (int a = 0; a < 4; a++) {
            int k = kg * 4 + a;
            size_t off = ((size_t)bi * KM + k) * MY + m;
            float2 r0 = up2(cr[a][0]), r1 = up2(cr[a][1]);
            float2 i0 = up2(ci[a][0]), i1 = up2(ci[a][1]);
            *(float4*)&g_ftxr[off] = make_float4(r0.x, r0.y, r1.x, r1.y);
            *(float4*)&g_ftxi[off] = make_float4(i0.x, i0.y, i1.x, i1.y);
        }
    }
}

// ---------------- mode mix: per (b,k): OUT[o][l] = sum_i W[i][o] * F[i][l] (complex) ----------------
__global__ void mixK(const float* __restrict__ fw,
                     const float* __restrict__ finr, const float* __restrict__ fini,
                     float* __restrict__ foutr, float* __restrict__ fouti, int L) {
    int b = blockIdx.z, k = blockIdx.y;
    int l0 = blockIdx.x * 128;
    int tid = threadIdx.x;
    int og = tid >> 5, lg = tid & 31;

    __shared__ float  sWr[32][32], sWi[32][32];
    __shared__ float4 sFr[32][32], sFi[32][32];

    for (int idx = tid; idx < 1024; idx += 256) {
        int i = idx >> 5, o = idx & 31;
        const float* p = fw + ((size_t)(i * 32 + o) * KM + k) * 2;
        sWr[i][o] = p[0]; sWi[i][o] = p[1];
    }
    for (int idx = tid; idx < 1024; idx += 256) {
        int i = idx >> 5, l4 = idx & 31;
        int gl = l0 + l4 * 4;
        if (gl < L) {
            size_t off = ((size_t)(b * CW + i) * KM + k) * L + gl;
            sFr[i][l4] = *(const float4*)&finr[off];
            sFi[i][l4] = *(const float4*)&fini[off];
        } else {
            sFr[i][l4] = make_float4(0.f, 0.f, 0.f, 0.f);
            sFi[i][l4] = make_float4(0.f, 0.f, 0.f, 0.f);
        }
    }
    __syncthreads();

    ull cr[4][2], ci[4][2];
#pragma unroll
    for (int a = 0; a < 4; a++) { cr[a][0] = cr[a][1] = 0ULL; ci[a][0] = ci[a][1] = 0ULL; }

#pragma unroll 2
    for (int i = 0; i < 32; i++) {
        float4 fr = sFr[i][lg], fi = sFi[i][lg];
        ull fr01 = pk2(fr.x, fr.y), fr23 = pk2(fr.z, fr.w);
        ull fi01 = pk2(fi.x, fi.y), fi23 = pk2(fi.z, fi.w);
        float4 wr = *(const float4*)&sWr[i][og * 4];
        float4 wi = *(const float4*)&sWi[i][og * 4];
        const float* wrp = &wr.x; const float* wip = &wi.x;
#pragma unroll
        for (int a = 0; a < 4; a++) {
            float wrv = wrp[a], wiv = wip[a];
            ull wrd = pk2(wrv, wrv);
            ull wid = pk2(wiv, wiv);
            ull wnd = pk2(-wiv, -wiv);
            fma2(cr[a][0], wrd, fr01); fma2(cr[a][0], wnd, fi01);
            fma2(cr[a][1], wrd, fr23); fma2(cr[a][1], wnd, fi23);
            fma2(ci[a][0], wrd, fi01); fma2(ci[a][0], wid, fr01);
            fma2(ci[a][1], wrd, fi23); fma2(ci[a][1], wid, fr23);
        }
    }
    int gl = l0 + lg * 4;
    if (gl < L) {
#pragma unroll
        for (int a = 0; a < 4; a++) {
            int o = og * 4 + a;
            size_t off = ((size_t)(b * CW + o) * KM + k) * L + gl;
            float2 r0 = up2(cr[a][0]), r1 = up2(cr[a][1]);
            float2 i0 = up2(ci[a][0]), i1 = up2(ci[a][1]);
            *(float4*)&foutr[off] = make_float4(r0.x, r0.y, r1.x, r1.y);
            *(float4*)&fouti[off] = make_float4(i0.x, i0.y, i1.x, i1.y);
        }
    }
}

// ---------------- fused inverse: x1[m][n] = invY + invX ----------------
__global__ void invK() {
    int bo = blockIdx.z;
    int m0 = blockIdx.y * 64;
    int n0 = blockIdx.x * 64;
    int tid = threadIdx.x;
    int mg = tid >> 4, ng = tid & 15;
    int mlim = (m0 == 128) ? 13 : 16;
    int nlim = (n0 == 320) ? 10 : 16;

    __shared__ float4 sVyr[16][16], sVyi[16][16], sOyr[16][16], sOyi[16][16];
    __shared__ float4 sOxr[16][16], sOxi[16][16], sVxr[16][16], sVxi[16][16];

    ull acc[4][2];
#pragma unroll
    for (int a = 0; a < 4; a++) { acc[a][0] = acc[a][1] = 0ULL; }

    for (int kc = 0; kc < KM; kc += 16) {
        int kk = tid >> 4, q = tid & 15;
        int kabs = kc + kk;
        float4 z = make_float4(0.f, 0.f, 0.f, 0.f);
        bool mv = q < mlim, nv = q < nlim;
        size_t obY = ((size_t)bo * KM + kabs) * NX + n0 + q * 4;
        size_t obX = ((size_t)bo * KM + kabs) * MY + m0 + q * 4;
        sVyr[kk][q] = mv ? *(const float4*)&g_Vyr[kabs * MY + m0 + q * 4] : z;
        sVyi[kk][q] = mv ? *(const float4*)&g_Vyi[kabs * MY + m0 + q * 4] : z;
        sOxr[kk][q] = mv ? *(const float4*)&g_oxr[obX] : z;
        sOxi[kk][q] = mv ? *(const float4*)&g_oxi[obX] : z;
        sOyr[kk][q] = nv ? *(const float4*)&g_oyr[obY] : z;
        sOyi[kk][q] = nv ? *(const float4*)&g_oyi[obY] : z;
        sVxr[kk][q] = nv ? *(const float4*)&g_Vxr[kabs * NX + n0 + q * 4] : z;
        sVxi[kk][q] = nv ? *(const float4*)&g_Vxi[kabs * NX + n0 + q * 4] : z;
        __syncthreads();

#pragma unroll 4
        for (int j = 0; j < 16; j++) {
            float4 vyr = sVyr[j][mg], vyi = sVyi[j][mg];
            float4 oxr = sOxr[j][mg], oxi = sOxi[j][mg];
            float4 oyr = sOyr[j][ng], oyi = sOyi[j][ng];
            float4 vxr = sVxr[j][ng], vxi = sVxi[j][ng];
            ull oyr01 = pk2(oyr.x, oyr.y), oyr23 = pk2(oyr.z, oyr.w);
            ull oyi01 = pk2(oyi.x, oyi.y), oyi23 = pk2(oyi.z, oyi.w);
            ull vxr01 = pk2(vxr.x, vxr.y), vxr23 = pk2(vxr.z, vxr.w);
            ull vxi01 = pk2(vxi.x, vxi.y), vxi23 = pk2(vxi.z, vxi.w);
            const float* ayr = &vyr.x; const float* ayi = &vyi.x;
            const float* axr = &oxr.x; const float* axi = &oxi.x;
#pragma unroll
            for (int a = 0; a < 4; a++) {
                ull vyrd = pk2(ayr[a], ayr[a]);
                ull vyid = pk2(ayi[a], ayi[a]);
                ull oxrd = pk2(axr[a], axr[a]);
                ull oxid = pk2(axi[a], axi[a]);
                fma2(acc[a][0], vyrd, oyr01); fma2(acc[a][0], vyid, oyi01);
                fma2(acc[a][0], oxrd, vxr01); fma2(acc[a][0], oxid, vxi01);
                fma2(acc[a][1], vyrd, oyr23); fma2(acc[a][1], vyid, oyi23);
                fma2(acc[a][1], oxrd, vxr23); fma2(acc[a][1], oxid, vxi23);
            }
        }
        __syncthreads();
    }

    if (ng < nlim && mg < mlim) {
        float* xb = g_x1 + (size_t)bo * PLANE;
        int n = n0 + ng * 4;
#pragma unroll
        for (int a = 0; a < 4; a++) {
            int m = m0 + mg * 4 + a;
            float2 u0 = up2(acc[a][0]), u1 = up2(acc[a][1]);
            *(float4*)&xb[m * NX + n] = make_float4(u0.x, u0.y, u1.x, u1.y);
        }
    }
}

// ---------------- pointwise MLP + residual: tile 128 pixels ----------------
__global__ void pwK(const float* __restrict__ w1, const float* __restrict__ b1,
                    const float* __restrict__ w2, const float* __restrict__ b2,
                    int applyGelu) {
    __shared__ float sX[32][128];
    __shared__ float sT[32][132];
    __shared__ float sW1[32][32], sW2[32][32];
    __shared__ float sB1[32], sB2[32];
    int tid = threadIdx.x;
    for (int idx = tid; idx < 1024; idx += 256) {
        int o = idx >> 5, c = idx & 31;
        sW1[c][o] = w1[o * 32 + c];
        sW2[c][o] = w2[o * 32 + c];
    }
    if (tid < 32) { sB1[tid] = b1[tid]; sB2[tid] = b2[tid]; }

    int p0 = blockIdx.x * 128;
    {
        int pp = tid & 127, ch = (tid >> 7) * 16;
        int p = p0 + pp;
        int b = p / PLANE, mn = p % PLANE;
        const float* src = g_x1 + ((size_t)b * CW + ch) * PLANE + mn;
#pragma unroll
        for (int cc = 0; cc < 16; cc++) sX[ch + cc][pp] = src[(size_t)cc * PLANE];
    }
    __syncthreads();

    int og = tid >> 5, pg = tid & 31;
    // stage 1: T = gelu(W1 X + b1)
    {
        ull t[4][2];
#pragma unroll
        for (int a = 0; a < 4; a++) { float bb = sB1[og * 4 + a]; t[a][0] = t[a][1] = pk2(bb, bb); }
#pragma unroll 4
        for (int c = 0; c < 32; c++) {
            float4 x4 = *(const float4*)&sX[c][pg * 4];
            ull x01 = pk2(x4.x, x4.y), x23 = pk2(x4.z, x4.w);
            float4 w4 = *(const float4*)&sW1[c][og * 4];
            const float* wv = &w4.x;
#pragma unroll
            for (int a = 0; a < 4; a++) {
                ull wd = pk2(wv[a], wv[a]);
                fma2(t[a][0], wd, x01); fma2(t[a][1], wd, x23);
            }
        }
#pragma unroll
        for (int a = 0; a < 4; a++) {
            float2 u0 = up2(t[a][0]), u1 = up2(t[a][1]);
            *(float4*)&sT[og * 4 + a][pg * 4] =
                make_float4(geluf(u0.x), geluf(u0.y), geluf(u1.x), geluf(u1.y));
        }
    }
    __syncthreads();
    // stage 2: out = [gelu](W2 T + b2) + h
    {
        ull t[4][2];
#pragma unroll
        for (int a = 0; a < 4; a++) { float bb = sB2[og * 4 + a]; t[a][0] = t[a][1] = pk2(bb, bb); }
#pragma unroll 4
        for (int c = 0; c < 32; c++) {
            float4 x4 = *(const float4*)&sT[c][pg * 4];
            ull x01 = pk2(x4.x, x4.y), x23 = pk2(x4.z, x4.w);
            float4 w4 = *(const float4*)&sW2[c][og * 4];
            const float* wv = &w4.x;
#pragma unroll
            for (int a = 0; a < 4; a++) {
                ull wd = pk2(wv[a], wv[a]);
                fma2(t[a][0], wd, x01); fma2(t[a][1], wd, x23);
            }
        }
        int pbase = p0 + pg * 4;
#pragma unroll
        for (int a = 0; a < 4; a++) {
            int o = og * 4 + a;
            float2 u0 = up2(t[a][0]), u1 = up2(t[a][1]);
            float v[4] = {u0.x, u0.y, u1.x, u1.y};
#pragma unroll
            for (int j = 0; j < 4; j++) {
                int p = pbase + j;
                int b = p / PLANE, mn = p % PLANE;
                size_t off = ((size_t)b * CW + o) * PLANE + mn;
                float s = v[j];
                if (applyGelu) s = geluf(s);
                g_h[off] += s;
            }
        }
    }
}

// ---------------- final head: tile 64 pixels ----------------
__global__ void finalK(const float* __restrict__ fc1w, const float* __restrict__ fc1b,
                       const float* __restrict__ fc2w, const float* __restrict__ fc2b,
                       float* __restrict__ out) {
    __shared__ float sX[32][68];
    __shared__ float sW1h[32][64];
    __shared__ float sT[64][68];
    __shared__ float sw2[128], sb1[128];
    __shared__ float sRed[4][64];
    int tid = threadIdx.x;
    if (tid < 128) { sw2[tid] = fc2w[tid]; sb1[tid] = fc1b[tid]; }

    int p0 = blockIdx.x * 64;
    {
        int pp = tid & 63, ch = (tid >> 6) * 8;
        int p = p0 + pp;
        int b = p / PLANE, mn = p % PLANE;
        const float* src = g_h + ((size_t)b * CW + ch) * PLANE + mn;
#pragma unroll
        for (int cc = 0; cc < 8; cc++) sX[ch + cc][pp] = src[(size_t)cc * PLANE];
    }

    float part = 0.f;
    for (int jh = 0; jh < 128; jh += 64) {
        __syncthreads();
        for (int idx = tid; idx < 512; idx += 256) {
            int c = idx >> 4, j4 = idx & 15;
            *(float4*)&sW1h[c][j4 * 4] = *(const float4*)&fc1w[c * 128 + jh + j4 * 4];
        }
        __syncthreads();

        int jg = tid >> 4, pgr = tid & 15;
        ull t[4][2];
#pragma unroll
        for (int a = 0; a < 4; a++) { float bb = sb1[jh + jg * 4 + a]; t[a][0] = t[a][1] = pk2(bb, bb); }
#pragma unroll 4
        for (int c = 0; c < 32; c++) {
            float4 x4 = *(const float4*)&sX[c][pgr * 4];
            ull x01 = pk2(x4.x, x4.y), x23 = pk2(x4.z, x4.w);
            float4 w4 = *(const float4*)&sW1h[c][jg * 4];
            const float* wv = &w4.x;
#pragma unroll
            for (int a = 0; a < 4; a++) {
                ull wd = pk2(wv[a], wv[a]);
                fma2(t[a][0], wd, x01); fma2(t[a][1], wd, x23);
            }
        }
#pragma unroll
        for (int a = 0; a < 4; a++) {
            float2 u0 = up2(t[a][0]), u1 = up2(t[a][1]);
            *(float4*)&sT[jg * 4 + a][pgr * 4] =
                make_float4(geluf(u0.x), geluf(u0.y), geluf(u1.x), geluf(u1.y));
        }
        __syncthreads();
        {
            int pq = tid & 63, jq = tid >> 6;
            float s = 0.f;
#pragma unroll
            for (int jj = 0; jj < 16; jj++) {
                int j = jq * 16 + jj;
                s = fmaf(sw2[jh + j], sT[j][pq], s);
            }
            part += s;
        }
    }
    __syncthreads();
    {
        int pq = tid & 63, jq = tid >> 6;
        sRed[jq][pq] = part;
    }
    __syncthreads();
    if (tid < 64) {
        out[p0 + tid] = sRed[0][tid] + sRed[1][tid] + sRed[2][tid] + sRed[3][tid] + fc2b[0];
    }
}

// ---------------- launch ----------------
extern "C" void kernel_launch(void* const* d_in, const int* in_sizes, int n_in,
                              void* d_out, int out_size) {
    (void)in_sizes; (void)n_in; (void)out_size;
    const float* x    = (const float*)d_in[0];
    const float* sx   = (const float*)d_in[1];
    const float* sy   = (const float*)d_in[2];
    const float* fc0w = (const float*)d_in[3];
    const float* fc0b = (const float*)d_in[4];
    const float* fw1  = (const float*)d_in[5];
    const float* fw2  = (const float*)d_in[6];
    const float* w1   = (const float*)d_in[7];
    const float* b1   = (const float*)d_in[8];
    const float* w2   = (const float*)d_in[9];
    const float* b2   = (const float*)d_in[10];
    const float* fc1w = (const float*)d_in[11];
    const float* fc1b = (const float*)d_in[12];
    const float* fc2w = (const float*)d_in[13];
    const float* fc2b = (const float*)d_in[14];
    float* out = (float*)d_out;

    precomputeK<<<64, 256>>>(sx, sy);
    fc0K<<<PIX / 128, 256>>>(x, fc0w, fc0b);

    for (int blk = 0; blk < 4; blk++) {
        const float* fw1p = fw1 + (size_t)blk * CW * CW * KM * 2;
        const float* fw2p = fw2 + (size_t)blk * CW * CW * KM * 2;
        const float* w1p  = w1 + (size_t)blk * CW * CW;
        const float* b1p  = b1 + (size_t)blk * CW;
        const float* w2p  = w2 + (size_t)blk * CW * CW;
        const float* b2p  = b2 + (size_t)blk * CW;

        ftyK<<<dim3(3, BSZ * CW), 256>>>();
        mixK<<<dim3(3, KM, BSZ), 256>>>(fw1p, g_ftyr, g_ftyi, g_oyr, g_oyi, NX);
        ftxK<<<dim3(2, BSZ * CW), 256>>>();
        mixK<<<dim3(2, KM, BSZ), 256>>>(fw2p, g_ftxr, g_ftxi, g_oxr, g_oxi, MY);
        invK<<<dim3(6, 3, BSZ * CW), 256>>>();
        pwK<<<PIX / 128, 256>>>(w1p, b1p, w2p, b2p, blk < 3 ? 1 : 0);
    }

    finalK<<<PIX / 64, 256>>>(fc1w, fc1b, fc2w, fc2b, out);
}